// round 1
// baseline (speedup 1.0000x reference)
#include <cuda_runtime.h>
#include <cstdint>

#define NB 2
#define NN 8192
#define NI 32
#define NE 128
#define NP (NB*NN)      // 16384 points
#define NBI (NB*NI)     // 64 (b,i) rows
#define NWORDS (NN/32)  // 256 mask words per (b,i)

// ---------------- device scratch (no allocations allowed) ----------------
__device__ float    g_U[(size_t)NP*64];       // pf @ Wd1^T   (4 MB)
__device__ float    g_pe[NBI*NE];             // pos_embed
__device__ float    g_V1[NBI*64];             // pe@Wd1^T + bd1
__device__ float    g_V2[NBI*64];             // (pe-ne)@Wd1^T + bd1
__device__ float    g_dpe[NBI*NE];            // pe - ne
__device__ unsigned g_mask[NBI*NWORDS];       // initial masks bitmaps
__device__ int      g_inter[NBI*NI];          // mask intersections

// ---------------- packed f32x2 helpers (Blackwell FFMA2) ----------------
__device__ __forceinline__ unsigned long long ffma2(unsigned long long a,
                                                    unsigned long long b,
                                                    unsigned long long c) {
  unsigned long long d;
  asm("fma.rn.f32x2 %0, %1, %2, %3;" : "=l"(d) : "l"(a), "l"(b), "l"(c));
  return d;
}
__device__ __forceinline__ unsigned long long pack2(float lo, float hi) {
  unsigned long long r;
  asm("mov.b64 %0, {%1, %2};" : "=l"(r) : "f"(lo), "f"(hi));
  return r;
}
__device__ __forceinline__ float lo2(unsigned long long v) {
  float a; asm("{ .reg .f32 t; mov.b64 {%0, t}, %1; }" : "=f"(a) : "l"(v)); return a;
}
__device__ __forceinline__ float hi2(unsigned long long v) {
  float a; asm("{ .reg .f32 t; mov.b64 {t, %0}, %1; }" : "=f"(a) : "l"(v)); return a;
}

// ---------------- threefry2x32 (JAX partitionable path) ----------------
__device__ __forceinline__ unsigned tf_rotl(unsigned x, int r) {
  return (x << r) | (x >> (32 - r));
}
__device__ unsigned threefry_bits32(unsigned k0, unsigned k1, unsigned x0, unsigned x1) {
  unsigned ks0 = k0, ks1 = k1, ks2 = 0x1BD11BDAu ^ k0 ^ k1;
  x0 += ks0; x1 += ks1;
#define TFR(r) { x0 += x1; x1 = tf_rotl(x1, r); x1 ^= x0; }
  TFR(13) TFR(15) TFR(26) TFR(6)   x0 += ks1; x1 += ks2 + 1u;
  TFR(17) TFR(29) TFR(16) TFR(24)  x0 += ks2; x1 += ks0 + 2u;
  TFR(13) TFR(15) TFR(26) TFR(6)   x0 += ks0; x1 += ks1 + 3u;
  TFR(17) TFR(29) TFR(16) TFR(24)  x0 += ks1; x1 += ks2 + 4u;
  TFR(13) TFR(15) TFR(26) TFR(6)   x0 += ks2; x1 += ks0 + 5u;
#undef TFR
  return x0 ^ x1;   // 32-bit output of partitionable random_bits
}

// ---------------- encoder: point_feats + U = pf @ Wd1^T ----------------
// shared layout (floats)
#define OFF_W1   0        // 192
#define OFF_A1   192      // 12
#define OFF_B1   204      // 256
#define OFF_W2   464      // 8192   (8B aligned)
#define OFF_A2   8656     // 256
#define OFF_B2   8912     // 512
#define OFF_WD1T 9424     // 8192   (transposed [e][k])
#define OFF_PF   17616    // 128*33 staging
#define ENC_SMEM_FLOATS (17616 + 128*33)
#define ENC_SMEM_BYTES  (ENC_SMEM_FLOATS * 4)

__global__ void __launch_bounds__(128) enc_kernel(
    const float* __restrict__ points, const float* __restrict__ W1,
    const float* __restrict__ A1, const float* __restrict__ B1,
    const float* __restrict__ W2, const float* __restrict__ A2,
    const float* __restrict__ B2, const float* __restrict__ Wd1,
    float* __restrict__ pf_out)
{
  extern __shared__ float sm[];
  float* sW1   = sm + OFF_W1;
  float* sA1   = sm + OFF_A1;
  float* sB1   = sm + OFF_B1;
  float* sW2   = sm + OFF_W2;
  float* sA2   = sm + OFF_A2;
  float* sB2   = sm + OFF_B2;
  float* sWd1T = sm + OFF_WD1T;
  float* sPF   = sm + OFF_PF;
  const int tid = threadIdx.x;

  for (int t = tid; t < 192; t += 128) sW1[t] = W1[t];
  if (tid < 12) sA1[tid] = A1[tid];
  for (int t = tid; t < 256; t += 128) sB1[t] = B1[t];
  for (int t = tid; t < 8192; t += 128) sW2[t] = W2[t];
  for (int t = tid; t < 256; t += 128) sA2[t] = A2[t];
  for (int t = tid; t < 512; t += 128) sB2[t] = B2[t];
  for (int t = tid; t < 8192; t += 128) { int k = t >> 7, e = t & 127; sWd1T[e*64 + k] = Wd1[t]; }
  __syncthreads();

  const int pbase = blockIdx.x * 128;
  const int p = pbase + tid;
  const float x0 = points[p*3+0], x1 = points[p*3+1], x2 = points[p*3+2];

  float a1v[4];
#pragma unroll
  for (int s = 0; s < 4; s++)
    a1v[s] = sA1[s*3+0]*x0 + sA1[s*3+1]*x1 + sA1[s*3+2]*x2;

  float h[64];
#pragma unroll
  for (int o = 0; o < 64; o++) {
    float v = sW1[o*3+0]*x0 + sW1[o*3+1]*x1 + sW1[o*3+2]*x2;
    v += 0.25f * (sB1[o*4+0]*a1v[0] + sB1[o*4+1]*a1v[1] +
                  sB1[o*4+2]*a1v[2] + sB1[o*4+3]*a1v[3]);
    h[o] = fmaxf(v, 0.0f);
  }

  unsigned long long hp[32];
#pragma unroll
  for (int q = 0; q < 32; q++) hp[q] = pack2(h[2*q], h[2*q+1]);

  float a2v[4];
#pragma unroll
  for (int s = 0; s < 4; s++) {
    const unsigned long long* A2p = (const unsigned long long*)(sA2 + s*64);
    unsigned long long acc = 0ull;
#pragma unroll
    for (int q = 0; q < 32; q++) acc = ffma2(A2p[q], hp[q], acc);
    a2v[s] = lo2(acc) + hi2(acc);
  }

  unsigned long long Up[32];
#pragma unroll
  for (int q = 0; q < 32; q++) Up[q] = 0ull;

  for (int jc = 0; jc < 128; jc += 32) {
#pragma unroll 1
    for (int jj = 0; jj < 32; jj++) {
      const int j = jc + jj;
      const unsigned long long* w2p = (const unsigned long long*)(sW2 + j*64);
      unsigned long long acc0 = 0ull, acc1 = 0ull;
#pragma unroll
      for (int q = 0; q < 32; q += 2) {
        acc0 = ffma2(w2p[q],   hp[q],   acc0);
        acc1 = ffma2(w2p[q+1], hp[q+1], acc1);
      }
      float pf = (lo2(acc0) + hi2(acc0)) + (lo2(acc1) + hi2(acc1));
      pf += 0.25f * (sB2[j*4+0]*a2v[0] + sB2[j*4+1]*a2v[1] +
                     sB2[j*4+2]*a2v[2] + sB2[j*4+3]*a2v[3]);
      sPF[tid*33 + jj] = pf;
      const unsigned long long pfb = pack2(pf, pf);
      const unsigned long long* wtp = (const unsigned long long*)(sWd1T + j*64);
#pragma unroll
      for (int q = 0; q < 32; q++) Up[q] = ffma2(wtp[q], pfb, Up[q]);
    }
    __syncthreads();
#pragma unroll
    for (int m = 0; m < 32; m++) {
      int lin = m*128 + tid;
      int r = lin >> 5, c = lin & 31;
      pf_out[(size_t)(pbase + r)*128 + jc + c] = sPF[r*33 + c];
    }
    __syncthreads();
  }

  float2* ud = (float2*)(g_U + (size_t)p*64);
#pragma unroll
  for (int q = 0; q < 32; q++) ud[q] = make_float2(lo2(Up[q]), hi2(Up[q]));
}

// ---------------- pos_embed + V1 ----------------
__global__ void pe_kernel(const float* __restrict__ pos_coords,
                          const float* __restrict__ Wp, const float* __restrict__ bp,
                          const float* __restrict__ Wd1, const float* __restrict__ bd1)
{
  const int bi = blockIdx.x;   // 0..63
  const int t = threadIdx.x;   // 128
  __shared__ float spe[128];
  const float p0 = pos_coords[bi*3+0], p1 = pos_coords[bi*3+1], p2 = pos_coords[bi*3+2];
  {
    float v = Wp[t*3+0]*p0 + Wp[t*3+1]*p1 + Wp[t*3+2]*p2 + bp[t];
    spe[t] = v;
    g_pe[bi*NE + t] = v;
  }
  __syncthreads();
  if (t < 64) {
    const float* w = Wd1 + t*128;
    float acc = 0.0f;
#pragma unroll
    for (int e = 0; e < 128; e++) acc = fmaf(w[e], spe[e], acc);
    g_V1[bi*64 + t] = acc + bd1[t];
  }
}

// ---------------- decode: masks (INIT) or refined logits ----------------
template<bool WRITE_LOGITS>
__global__ void __launch_bounds__(256) decode_kernel(
    const float* __restrict__ wd2p, const float* __restrict__ bd2p,
    float* __restrict__ out)
{
  __shared__ float sV[32*64];
  __shared__ float swd2[64];
  const int b = blockIdx.y;
  const int tid = threadIdx.x;
  const float* Vtab = WRITE_LOGITS ? g_V2 : g_V1;
  for (int t = tid; t < 32*64; t += 256) sV[t] = Vtab[b*32*64 + t];
  if (tid < 64) swd2[tid] = wd2p[tid];
  __syncthreads();

  const int n = blockIdx.x*256 + tid;
  float u[64];
  const float4* up = (const float4*)(g_U + (size_t)(b*NN + n)*64);
#pragma unroll
  for (int q = 0; q < 16; q++) {
    float4 v = up[q];
    u[q*4+0] = v.x; u[q*4+1] = v.y; u[q*4+2] = v.z; u[q*4+3] = v.w;
  }
  const float bd2 = bd2p[0];

#pragma unroll 1
  for (int i = 0; i < 32; i++) {
    const float* vv = &sV[i*64];
    float a0 = 0.f, a1 = 0.f, a2 = 0.f, a3 = 0.f;
#pragma unroll
    for (int k = 0; k < 64; k += 4) {
      a0 = fmaf(fmaxf(u[k+0] + vv[k+0], 0.f), swd2[k+0], a0);
      a1 = fmaf(fmaxf(u[k+1] + vv[k+1], 0.f), swd2[k+1], a1);
      a2 = fmaf(fmaxf(u[k+2] + vv[k+2], 0.f), swd2[k+2], a2);
      a3 = fmaf(fmaxf(u[k+3] + vv[k+3], 0.f), swd2[k+3], a3);
    }
    float acc = ((a0 + a1) + (a2 + a3)) + bd2;
    if (WRITE_LOGITS) {
      out[(size_t)(b*32 + i)*NN + n] = acc;
    } else {
      unsigned m = __ballot_sync(0xFFFFFFFFu, acc > 0.0f);
      if ((tid & 31) == 0) g_mask[(b*32 + i)*NWORDS + (n >> 5)] = m;
    }
  }
}

// ---------------- mask intersections ----------------
__global__ void inter_kernel()
{
  const int w = (blockIdx.x * blockDim.x + threadIdx.x) >> 5;  // 0..2047
  const int lane = threadIdx.x & 31;
  const int bi = w >> 5;            // 0..63
  const int j  = w & 31;
  const int b  = bi >> 5;
  const unsigned* mi = g_mask + (size_t)bi * NWORDS;
  const unsigned* mj = g_mask + (size_t)(b*32 + j) * NWORDS;
  int s = 0;
#pragma unroll
  for (int c = 0; c < 8; c++) s += __popc(mi[c*32 + lane] & mj[c*32 + lane]);
  s = __reduce_add_sync(0xFFFFFFFFu, s);
  if (lane == 0) g_inter[bi*NI + j] = s;
}

// ---------------- iou + gumbel-max sampling + dpe = pe - ne ----------------
__global__ void sample_kernel(const float* __restrict__ pos_coords,
                              const float* __restrict__ Wp,
                              const float* __restrict__ bp)
{
  __shared__ float s_ms[64];
  __shared__ int s_idx[64];
  __shared__ int s_valid[64];
  const int tid = threadIdx.x;  // 256
  if (tid < 64) s_ms[tid] = (float)g_inter[tid*NI + (tid & 31)];  // diagonal = m_sum
  __syncthreads();
  if (tid < 64) {
    const int bi = tid, b = bi >> 5, i = bi & 31;
    const float msi = s_ms[bi];
    unsigned bestkey = 0u;
    int bestj = -1;
    for (int j = 0; j < 32; j++) {
      if (j == i) continue;
      float inter = (float)g_inter[bi*NI + j];
      float un = msi + s_ms[b*32 + j] - inter;
      float iou = __fdiv_rn(inter, un + 1e-6f);
      if (iou >= 0.1f) {
        unsigned bits = threefry_bits32(0u, 42u, 0u, (unsigned)(bi*32 + j));
        unsigned key = bits >> 9;  // monotone proxy for gumbel(-log(-log u))
        if (bestj < 0 || key > bestkey) { bestkey = key; bestj = j; }
      }
    }
    s_idx[bi] = bestj;
    s_valid[bi] = (bestj >= 0);
  }
  __syncthreads();
  for (int e = tid; e < 64*128; e += 256) {
    const int bi = e >> 7, c = e & 127, b = bi >> 5;
    float n0 = 0.f, n1 = 0.f, n2 = 0.f;
    if (s_valid[bi]) {
      const float* pc = pos_coords + (size_t)(b*32 + s_idx[bi]) * 3;
      n0 = pc[0]; n1 = pc[1]; n2 = pc[2];
    }
    float ne = Wp[c*3+0]*n0 + Wp[c*3+1]*n1 + Wp[c*3+2]*n2 + bp[c];
    g_dpe[bi*NE + c] = g_pe[bi*NE + c] - ne;
  }
}

// ---------------- V2 = dpe @ Wd1^T + bd1 ----------------
__global__ void v2_kernel(const float* __restrict__ Wd1, const float* __restrict__ bd1)
{
  const int bi = blockIdx.x;   // 64
  const int k = threadIdx.x;   // 64
  __shared__ float sd[128];
  for (int e = k; e < 128; e += 64) sd[e] = g_dpe[bi*NE + e];
  __syncthreads();
  const float* w = Wd1 + k*128;
  float acc = 0.0f;
#pragma unroll
  for (int e = 0; e < 128; e++) acc = fmaf(w[e], sd[e], acc);
  g_V2[bi*64 + k] = acc + bd1[k];
}

// ---------------- launch ----------------
extern "C" void kernel_launch(void* const* d_in, const int* in_sizes, int n_in,
                              void* d_out, int out_size)
{
  const float* points = (const float*)d_in[0];
  const float* pos    = (const float*)d_in[1];
  const float* W1     = (const float*)d_in[2];
  const float* A1     = (const float*)d_in[3];
  const float* B1     = (const float*)d_in[4];
  const float* W2     = (const float*)d_in[5];
  const float* A2     = (const float*)d_in[6];
  const float* B2     = (const float*)d_in[7];
  const float* Wp     = (const float*)d_in[8];
  const float* bp     = (const float*)d_in[9];
  const float* Wd1    = (const float*)d_in[10];
  const float* bd1    = (const float*)d_in[11];
  const float* Wd2    = (const float*)d_in[12];
  const float* bd2    = (const float*)d_in[13];

  float* out = (float*)d_out;
  float* refined = out;                              // [2,32,8192]
  float* pf_out  = out + (size_t)NB*NI*NN;           // [2,8192,128]

  cudaFuncSetAttribute(enc_kernel, cudaFuncAttributeMaxDynamicSharedMemorySize,
                       ENC_SMEM_BYTES);

  enc_kernel<<<NP/128, 128, ENC_SMEM_BYTES>>>(points, W1, A1, B1, W2, A2, B2, Wd1, pf_out);
  pe_kernel<<<NBI, 128>>>(pos, Wp, bp, Wd1, bd1);
  decode_kernel<false><<<dim3(NN/256, NB), 256>>>(Wd2, bd2, nullptr);
  inter_kernel<<<64, 1024>>>();
  sample_kernel<<<1, 256>>>(pos, Wp, bp);
  v2_kernel<<<NBI, 64>>>(Wd1, bd1);
  decode_kernel<true><<<dim3(NN/256, NB), 256>>>(Wd2, bd2, refined);
}

// round 4
// speedup vs baseline: 1.3750x; 1.3750x over previous
#include <cuda_runtime.h>
#include <cstdint>

#define NB 2
#define NN 8192
#define NI 32
#define NE 128
#define NP (NB*NN)      // 16384 points
#define NBI (NB*NI)     // 64 (b,i) rows

// ---------------- device scratch ----------------
__device__ float g_U[(size_t)NP*64];    // pf @ Wd1^T (4 MB)
__device__ float g_pe[NBI*NE];          // pos_embed
__device__ float g_V1[NBI*64];          // pe@Wd1^T + bd1
__device__ float g_V2[NBI*64];          // (pe-ne)@Wd1^T + bd1
__device__ int   g_inter[NBI*NI];       // mask intersections (atomic-accumulated)

// ---------------- packed f32x2 helpers ----------------
__device__ __forceinline__ unsigned long long ffma2(unsigned long long a,
                                                    unsigned long long b,
                                                    unsigned long long c) {
  unsigned long long d;
  asm("fma.rn.f32x2 %0, %1, %2, %3;" : "=l"(d) : "l"(a), "l"(b), "l"(c));
  return d;
}
__device__ __forceinline__ unsigned long long add2(unsigned long long a,
                                                   unsigned long long b) {
  unsigned long long d;
  asm("add.rn.f32x2 %0, %1, %2;" : "=l"(d) : "l"(a), "l"(b));
  return d;
}
__device__ __forceinline__ unsigned long long pack2(float lo, float hi) {
  unsigned long long r;
  asm("mov.b64 %0, {%1, %2};" : "=l"(r) : "f"(lo), "f"(hi));
  return r;
}
__device__ __forceinline__ float lo2(unsigned long long v) {
  float a; asm("{ .reg .f32 t; mov.b64 {%0, t}, %1; }" : "=f"(a) : "l"(v)); return a;
}
__device__ __forceinline__ float hi2(unsigned long long v) {
  float a; asm("{ .reg .f32 t; mov.b64 {t, %0}, %1; }" : "=f"(a) : "l"(v)); return a;
}

// ---------------- threefry2x32 (JAX partitionable path) ----------------
__device__ __forceinline__ unsigned tf_rotl(unsigned x, int r) {
  return (x << r) | (x >> (32 - r));
}
__device__ unsigned threefry_bits32(unsigned k0, unsigned k1, unsigned x0, unsigned x1) {
  unsigned ks0 = k0, ks1 = k1, ks2 = 0x1BD11BDAu ^ k0 ^ k1;
  x0 += ks0; x1 += ks1;
#define TFR(r) { x0 += x1; x1 = tf_rotl(x1, r); x1 ^= x0; }
  TFR(13) TFR(15) TFR(26) TFR(6)   x0 += ks1; x1 += ks2 + 1u;
  TFR(17) TFR(29) TFR(16) TFR(24)  x0 += ks2; x1 += ks0 + 2u;
  TFR(13) TFR(15) TFR(26) TFR(6)   x0 += ks0; x1 += ks1 + 3u;
  TFR(17) TFR(29) TFR(16) TFR(24)  x0 += ks1; x1 += ks2 + 4u;
  TFR(13) TFR(15) TFR(26) TFR(6)   x0 += ks2; x1 += ks0 + 5u;
#undef TFR
  return x0 ^ x1;
}

// ---------------- encoder (+pe fused): 64 pe blocks then 256 point blocks ----
// dyn-smem float layout
#define OFF_W1   0        // 192
#define OFF_A1   192      // 12
#define OFF_B1   204      // 256
#define OFF_W2   464      // 8192
#define OFF_A2   8656     // 256
#define OFF_B2   8912     // 512
#define OFF_WD1T 9424     // 8192  transposed [e][k]
#define OFF_ST   17616    // staging 128*67 = 8576 (reused as 64*65 for U-reduce)
#define ENC_SMEM_FLOATS (17616 + 8576)
#define ENC_SMEM_BYTES  (ENC_SMEM_FLOATS * 4)
#define ENC_PE_BLOCKS 64
#define ENC_PT_BLOCKS 256   // 64 points each

__global__ void __launch_bounds__(128) enc_kernel(
    const float* __restrict__ points, const float* __restrict__ pos_coords,
    const float* __restrict__ W1, const float* __restrict__ A1,
    const float* __restrict__ B1, const float* __restrict__ W2,
    const float* __restrict__ A2, const float* __restrict__ B2,
    const float* __restrict__ Wp, const float* __restrict__ bp,
    const float* __restrict__ Wd1, const float* __restrict__ bd1,
    float* __restrict__ pf_out)
{
  extern __shared__ float sm[];
  const int tid = threadIdx.x;

  if (blockIdx.x < ENC_PE_BLOCKS) {
    // ---- pos_embed + V1 + zero g_inter ----
    const int bi = blockIdx.x;
    float* spe = sm;
    if (tid < 32) g_inter[bi*32 + tid] = 0;
    const float p0 = pos_coords[bi*3+0], p1 = pos_coords[bi*3+1], p2 = pos_coords[bi*3+2];
    {
      float v = Wp[tid*3+0]*p0 + Wp[tid*3+1]*p1 + Wp[tid*3+2]*p2 + bp[tid];
      spe[tid] = v;
      g_pe[bi*NE + tid] = v;
    }
    __syncthreads();
    if (tid < 64) {
      const float* w = Wd1 + tid*128;
      float acc = 0.0f;
#pragma unroll
      for (int e = 0; e < 128; e++) acc = fmaf(w[e], spe[e], acc);
      g_V1[bi*64 + tid] = acc + bd1[tid];
    }
    return;
  }

  // ---- point blocks ----
  float* sW1   = sm + OFF_W1;
  float* sA1   = sm + OFF_A1;
  float* sB1   = sm + OFF_B1;
  float* sW2   = sm + OFF_W2;
  float* sA2   = sm + OFF_A2;
  float* sB2   = sm + OFF_B2;
  float* sWd1T = sm + OFF_WD1T;
  float* sST   = sm + OFF_ST;

  for (int t = tid; t < 192; t += 128) sW1[t] = W1[t];
  if (tid < 12) sA1[tid] = A1[tid];
  for (int t = tid; t < 256; t += 128) sB1[t] = B1[t];
  for (int t = tid; t < 8192; t += 128) sW2[t] = W2[t];
  for (int t = tid; t < 256; t += 128) sA2[t] = A2[t];
  for (int t = tid; t < 512; t += 128) sB2[t] = B2[t];
  for (int t = tid; t < 8192; t += 128) { int k = t >> 7, e = t & 127; sWd1T[e*64 + k] = Wd1[t]; }
  __syncthreads();

  const int pt   = tid & 63;
  const int half = tid >> 6;
  const int pbase = (blockIdx.x - ENC_PE_BLOCKS) * 64;
  const int p = pbase + pt;
  const float x0 = points[p*3+0], x1 = points[p*3+1], x2 = points[p*3+2];

  float a1v[4];
#pragma unroll
  for (int s = 0; s < 4; s++)
    a1v[s] = sA1[s*3+0]*x0 + sA1[s*3+1]*x1 + sA1[s*3+2]*x2;

  float h[64];
#pragma unroll
  for (int o = 0; o < 64; o++) {
    float v = sW1[o*3+0]*x0 + sW1[o*3+1]*x1 + sW1[o*3+2]*x2;
    v += 0.25f * (sB1[o*4+0]*a1v[0] + sB1[o*4+1]*a1v[1] +
                  sB1[o*4+2]*a1v[2] + sB1[o*4+3]*a1v[3]);
    h[o] = fmaxf(v, 0.0f);
  }

  unsigned long long hp[32];
#pragma unroll
  for (int q = 0; q < 32; q++) hp[q] = pack2(h[2*q], h[2*q+1]);

  float a2v[4];
#pragma unroll
  for (int s = 0; s < 4; s++) {
    const unsigned long long* A2p = (const unsigned long long*)(sA2 + s*64);
    unsigned long long acc = 0ull;
#pragma unroll
    for (int q = 0; q < 32; q++) acc = ffma2(A2p[q], hp[q], acc);
    a2v[s] = lo2(acc) + hi2(acc);
  }

  unsigned long long Up[32];
#pragma unroll
  for (int q = 0; q < 32; q++) Up[q] = 0ull;

  // this thread's 64 j outputs
#pragma unroll 1
  for (int jj = 0; jj < 64; jj++) {
    const int j = half*64 + jj;
    const unsigned long long* w2p = (const unsigned long long*)(sW2 + j*64);
    unsigned long long acc0 = 0ull, acc1 = 0ull;
#pragma unroll
    for (int q = 0; q < 32; q += 2) {
      acc0 = ffma2(w2p[q],   hp[q],   acc0);
      acc1 = ffma2(w2p[q+1], hp[q+1], acc1);
    }
    float pf = (lo2(acc0) + hi2(acc0)) + (lo2(acc1) + hi2(acc1));
    pf += 0.25f * (sB2[j*4+0]*a2v[0] + sB2[j*4+1]*a2v[1] +
                   sB2[j*4+2]*a2v[2] + sB2[j*4+3]*a2v[3]);
    sST[j*67 + pt] = pf;
    const unsigned long long pfb = pack2(pf, pf);
    const unsigned long long* wtp = (const unsigned long long*)(sWd1T + j*64);
#pragma unroll
    for (int q = 0; q < 32; q++) Up[q] = ffma2(wtp[q], pfb, Up[q]);
  }
  __syncthreads();

  // write pf_out: iteration it -> point it, lanes cover all 128 j (coalesced)
#pragma unroll 4
  for (int it = 0; it < 64; it++) {
    pf_out[(size_t)(pbase + it)*128 + tid] = sST[tid*67 + it];
  }
  __syncthreads();

  // U reduce across the two j-halves
  if (half == 1) {
#pragma unroll
    for (int q = 0; q < 32; q++) {
      sST[pt*65 + 2*q]     = lo2(Up[q]);
      sST[pt*65 + 2*q + 1] = hi2(Up[q]);
    }
  }
  __syncthreads();
  if (half == 0) {
    float4* ud = (float4*)(g_U + (size_t)p*64);
#pragma unroll
    for (int q = 0; q < 16; q++) {
      float4 v;
      v.x = lo2(Up[2*q])   + sST[pt*65 + 4*q];
      v.y = hi2(Up[2*q])   + sST[pt*65 + 4*q + 1];
      v.z = lo2(Up[2*q+1]) + sST[pt*65 + 4*q + 2];
      v.w = hi2(Up[2*q+1]) + sST[pt*65 + 4*q + 3];
      ud[q] = v;
    }
  }
}

// ---------------- decode ----------------
// MODE 0: masks -> per-block intersection partials (atomicAdd into g_inter)
// MODE 1: refined logits, i split in halves via blockIdx.z
template<int MODE>
__global__ void __launch_bounds__(128) decode_kernel(
    const float* __restrict__ wd2p, const float* __restrict__ bd2p,
    float* __restrict__ out)
{
  __shared__ unsigned long long sV[32*32];
  __shared__ unsigned long long sW[32];
  __shared__ unsigned sB[32*4];
  const int b = blockIdx.y;
  const int tid = threadIdx.x;
  const int ibase  = (MODE == 1) ? blockIdx.z * 16 : 0;
  const int icount = (MODE == 1) ? 16 : 32;
  const float* Vt = (MODE == 1) ? g_V2 : g_V1;

  for (int t = tid; t < icount*32; t += 128) {
    const int ii = t >> 5, kp = t & 31;
    sV[ii*32 + kp] = ((const unsigned long long*)(Vt + (size_t)(b*32 + ibase + ii)*64))[kp];
  }
  if (tid < 32) sW[tid] = pack2(0.5f*wd2p[2*tid], 0.5f*wd2p[2*tid+1]);
  __syncthreads();

  const int n = blockIdx.x*128 + tid;
  unsigned long long u2[32];
  const unsigned long long* up = (const unsigned long long*)(g_U + (size_t)(b*NN + n)*64);
#pragma unroll
  for (int q = 0; q < 32; q++) u2[q] = up[q];
  const float bd2 = bd2p[0];

#pragma unroll 1
  for (int ii = 0; ii < icount; ii++) {
    const unsigned long long* vv = sV + ii*32;
    unsigned long long a0 = 0ull, a1 = 0ull;
#pragma unroll
    for (int kp = 0; kp < 32; kp += 2) {
      // relu(x)*w == (x + |x|) * (w/2), bit-exact
      unsigned long long t0 = add2(u2[kp], vv[kp]);
      unsigned long long s0 = add2(t0, t0 & 0x7fffffff7fffffffULL);
      a0 = ffma2(s0, sW[kp], a0);
      unsigned long long t1 = add2(u2[kp+1], vv[kp+1]);
      unsigned long long s1 = add2(t1, t1 & 0x7fffffff7fffffffULL);
      a1 = ffma2(s1, sW[kp+1], a1);
    }
    float acc = ((lo2(a0) + hi2(a0)) + (lo2(a1) + hi2(a1))) + bd2;
    if (MODE == 1) {
      out[(size_t)(b*32 + ibase + ii)*NN + n] = acc;
    } else {
      unsigned m = __ballot_sync(0xFFFFFFFFu, acc > 0.0f);
      if ((tid & 31) == 0) sB[ii*4 + (tid >> 5)] = m;
    }
  }

  if (MODE == 0) {
    __syncthreads();
    // 1024 (i,j) pairs; diagonal pair gives m_sum
#pragma unroll
    for (int pr = 0; pr < 8; pr++) {
      const int pair = pr*128 + tid;
      const int i = pair >> 5, j = pair & 31;
      int v = 0;
#pragma unroll
      for (int c = 0; c < 4; c++) v += __popc(sB[i*4 + c] & sB[j*4 + c]);
      atomicAdd(&g_inter[(b*32 + i)*32 + j], v);
    }
  }
}

// ---------------- sampling + V2 (one block per (b,i)) ----------------
__global__ void __launch_bounds__(128) samplev2_kernel(
    const float* __restrict__ pos_coords, const float* __restrict__ Wp,
    const float* __restrict__ bp, const float* __restrict__ Wd1,
    const float* __restrict__ bd1)
{
  __shared__ float sdiag[32];
  __shared__ float srow[32];
  __shared__ float sc[3];
  __shared__ float sd[128];
  const int bi = blockIdx.x, b = bi >> 5, i = bi & 31;
  const int tid = threadIdx.x;

  if (tid < 32) {
    srow[tid]  = (float)g_inter[bi*32 + tid];
    sdiag[tid] = (float)g_inter[(b*32 + tid)*32 + tid];
  }
  __syncthreads();

  if (tid < 32) {
    const int j = tid;
    unsigned comb = 0u;
    if (j != i) {
      float inter = srow[j];
      float un = sdiag[i] + sdiag[j] - inter;
      float iou = __fdiv_rn(inter, un + 1e-6f);
      if (iou >= 0.1f) {
        unsigned bits = threefry_bits32(0u, 42u, 0u, (unsigned)(bi*32 + j));
        comb = (((bits >> 9) + 1u) << 6) | (unsigned)(31 - j);  // tie -> smaller j
      }
    }
    comb = __reduce_max_sync(0xFFFFFFFFu, comb);
    if (tid == 0) {
      if (comb != 0u) {
        const int j_sel = 31 - (int)(comb & 63u);
        const float* pc = pos_coords + (size_t)(b*32 + j_sel)*3;
        sc[0] = pc[0]; sc[1] = pc[1]; sc[2] = pc[2];
      } else {
        sc[0] = 0.f; sc[1] = 0.f; sc[2] = 0.f;
      }
    }
  }
  __syncthreads();

  {
    const int c = tid;
    float ne = Wp[c*3+0]*sc[0] + Wp[c*3+1]*sc[1] + Wp[c*3+2]*sc[2] + bp[c];
    sd[c] = g_pe[bi*NE + c] - ne;
  }
  __syncthreads();

  if (tid < 64) {
    const float* w = Wd1 + tid*128;
    float acc = 0.0f;
#pragma unroll
    for (int e = 0; e < 128; e++) acc = fmaf(w[e], sd[e], acc);
    g_V2[bi*64 + tid] = acc + bd1[tid];
  }
}

// ---------------- launch ----------------
extern "C" void kernel_launch(void* const* d_in, const int* in_sizes, int n_in,
                              void* d_out, int out_size)
{
  const float* points = (const float*)d_in[0];
  const float* pos    = (const float*)d_in[1];
  const float* W1     = (const float*)d_in[2];
  const float* A1     = (const float*)d_in[3];
  const float* B1     = (const float*)d_in[4];
  const float* W2     = (const float*)d_in[5];
  const float* A2     = (const float*)d_in[6];
  const float* B2     = (const float*)d_in[7];
  const float* Wp     = (const float*)d_in[8];
  const float* bp     = (const float*)d_in[9];
  const float* Wd1    = (const float*)d_in[10];
  const float* bd1    = (const float*)d_in[11];
  const float* Wd2    = (const float*)d_in[12];
  const float* bd2    = (const float*)d_in[13];

  float* out = (float*)d_out;
  float* refined = out;                       // [2,32,8192]
  float* pf_out  = out + (size_t)NB*NI*NN;    // [2,8192,128]

  cudaFuncSetAttribute(enc_kernel, cudaFuncAttributeMaxDynamicSharedMemorySize,
                       ENC_SMEM_BYTES);

  enc_kernel<<<ENC_PE_BLOCKS + ENC_PT_BLOCKS, 128, ENC_SMEM_BYTES>>>(
      points, pos, W1, A1, B1, W2, A2, B2, Wp, bp, Wd1, bd1, pf_out);
  decode_kernel<0><<<dim3(NN/128, NB), 128>>>(Wd2, bd2, nullptr);
  samplev2_kernel<<<NBI, 128>>>(pos, Wp, bp, Wd1, bd1);
  decode_kernel<1><<<dim3(NN/128, NB, 2), 128>>>(Wd2, bd2, refined);
}